// round 1
// baseline (speedup 1.0000x reference)
#include <cuda_runtime.h>
#include <math.h>
#include <float.h>

#define EPS 1e-8f
#define LR  0.1f

// Fixed problem dims (from reference): B=131072, S=1024, D=256
#define MAXB 131072
#define MAXS 2048
#define DD   256

// Scratch (no cudaMalloc allowed)
__device__ float g_kn[MAXS * DD];   // normalized keys
__device__ int   g_idx[MAXB];       // argmax per query row
__device__ int   g_winner[MAXS];    // max b writing to slot s (-1 = none)

// ---------------------------------------------------------------------------
// Kernel A: normalize keys (kn = keys / max(||k||, eps)), init winner = -1
// One block per key row, 256 threads (D=256).
// ---------------------------------------------------------------------------
__global__ void knorm_kernel(const float* __restrict__ keys, int S, int D) {
    int s = blockIdx.x;
    int t = threadIdx.x;
    __shared__ float red[8];
    __shared__ float s_nrm;

    float v = (t < D) ? keys[(size_t)s * D + t] : 0.0f;
    float sq = v * v;
    #pragma unroll
    for (int o = 16; o; o >>= 1) sq += __shfl_xor_sync(0xFFFFFFFFu, sq, o);
    if ((t & 31) == 0) red[t >> 5] = sq;
    __syncthreads();
    if (t == 0) {
        float tot = 0.0f;
        #pragma unroll
        for (int i = 0; i < 8; i++) tot += red[i];
        s_nrm = fmaxf(sqrtf(tot), EPS);
        g_winner[s] = -1;
    }
    __syncthreads();
    if (t < D) g_kn[(size_t)s * D + t] = v / s_nrm;
}

// ---------------------------------------------------------------------------
// Kernel B: fused scores GEMM + argmax.
// Tile: BM=64 query rows per block, loop over S in BN=128 key tiles,
// K (=D=256) in BK=64 chunks. 256 threads = 16x16, microtile 4 rows x 8 cols.
// Query tile (64 x 256) resident in smem for the whole block.
// ---------------------------------------------------------------------------
#define BM 64
#define BN 128
#define BK 64
#define AST 65   // Aq row stride (pad to kill store bank conflicts)

__global__ void __launch_bounds__(256, 2)
score_argmax_kernel(const float* __restrict__ q, int B, int S, int D) {
    extern __shared__ float sm[];
    float* Aq = sm;                 // [D][AST] k-major: Aq[k][m]
    float* Bs = sm + DD * AST;      // [BK][BN] k-major: Bs[k][n]

    const int tid = threadIdx.x;
    const int tx  = tid & 15;       // col group
    const int ty  = tid >> 4;       // row group
    const int bm0 = blockIdx.x * BM;

    // Load full query tile: 64 rows x 256 cols, store transposed Aq[k][m].
    {
        const float4* qb = (const float4*)(q + (size_t)bm0 * D);
        #pragma unroll
        for (int i = tid; i < BM * (DD / 4); i += 256) {
            int r  = i >> 6;          // row 0..63
            int c4 = i & 63;          // float4 col 0..63
            float4 v = qb[(size_t)r * (DD / 4) + c4];
            int k0 = c4 * 4;
            Aq[(k0 + 0) * AST + r] = v.x;
            Aq[(k0 + 1) * AST + r] = v.y;
            Aq[(k0 + 2) * AST + r] = v.z;
            Aq[(k0 + 3) * AST + r] = v.w;
        }
    }

    float best_v[4];
    int   best_i[4];
    #pragma unroll
    for (int i = 0; i < 4; i++) { best_v[i] = -FLT_MAX; best_i[i] = 0; }

    const int n_tiles = S / BN;
    for (int nt = 0; nt < n_tiles; nt++) {
        float acc[4][8];
        #pragma unroll
        for (int i = 0; i < 4; i++)
            #pragma unroll
            for (int j = 0; j < 8; j++) acc[i][j] = 0.0f;

        for (int kc = 0; kc < DD / BK; kc++) {
            __syncthreads();
            // Load kn chunk: rows nt*BN..+127, cols kc*BK..+63, transposed.
            const float* kb = g_kn + (size_t)(nt * BN) * D + kc * BK;
            #pragma unroll
            for (int i = tid; i < BN * (BK / 4); i += 256) {
                int n  = i >> 4;        // 0..127
                int c4 = i & 15;        // 0..15
                float4 v = *(const float4*)(kb + (size_t)n * D + c4 * 4);
                int k0 = c4 * 4;
                Bs[(k0 + 0) * BN + n] = v.x;
                Bs[(k0 + 1) * BN + n] = v.y;
                Bs[(k0 + 2) * BN + n] = v.z;
                Bs[(k0 + 3) * BN + n] = v.w;
            }
            __syncthreads();

            #pragma unroll 16
            for (int k = 0; k < BK; k++) {
                const float* arow = &Aq[(kc * BK + k) * AST + ty * 4];
                float a0 = arow[0], a1 = arow[1], a2 = arow[2], a3 = arow[3];
                float4 b0 = *(const float4*)&Bs[k * BN + tx * 4];
                float4 b1 = *(const float4*)&Bs[k * BN + 64 + tx * 4];
                acc[0][0] = fmaf(a0, b0.x, acc[0][0]);
                acc[0][1] = fmaf(a0, b0.y, acc[0][1]);
                acc[0][2] = fmaf(a0, b0.z, acc[0][2]);
                acc[0][3] = fmaf(a0, b0.w, acc[0][3]);
                acc[0][4] = fmaf(a0, b1.x, acc[0][4]);
                acc[0][5] = fmaf(a0, b1.y, acc[0][5]);
                acc[0][6] = fmaf(a0, b1.z, acc[0][6]);
                acc[0][7] = fmaf(a0, b1.w, acc[0][7]);
                acc[1][0] = fmaf(a1, b0.x, acc[1][0]);
                acc[1][1] = fmaf(a1, b0.y, acc[1][1]);
                acc[1][2] = fmaf(a1, b0.z, acc[1][2]);
                acc[1][3] = fmaf(a1, b0.w, acc[1][3]);
                acc[1][4] = fmaf(a1, b1.x, acc[1][4]);
                acc[1][5] = fmaf(a1, b1.y, acc[1][5]);
                acc[1][6] = fmaf(a1, b1.z, acc[1][6]);
                acc[1][7] = fmaf(a1, b1.w, acc[1][7]);
                acc[2][0] = fmaf(a2, b0.x, acc[2][0]);
                acc[2][1] = fmaf(a2, b0.y, acc[2][1]);
                acc[2][2] = fmaf(a2, b0.z, acc[2][2]);
                acc[2][3] = fmaf(a2, b0.w, acc[2][3]);
                acc[2][4] = fmaf(a2, b1.x, acc[2][4]);
                acc[2][5] = fmaf(a2, b1.y, acc[2][5]);
                acc[2][6] = fmaf(a2, b1.z, acc[2][6]);
                acc[2][7] = fmaf(a2, b1.w, acc[2][7]);
                acc[3][0] = fmaf(a3, b0.x, acc[3][0]);
                acc[3][1] = fmaf(a3, b0.y, acc[3][1]);
                acc[3][2] = fmaf(a3, b0.z, acc[3][2]);
                acc[3][3] = fmaf(a3, b0.w, acc[3][3]);
                acc[3][4] = fmaf(a3, b1.x, acc[3][4]);
                acc[3][5] = fmaf(a3, b1.y, acc[3][5]);
                acc[3][6] = fmaf(a3, b1.z, acc[3][6]);
                acc[3][7] = fmaf(a3, b1.w, acc[3][7]);
            }
        }

        // Per-thread argmax update (ascending global col order => first-max ties)
        #pragma unroll
        for (int j = 0; j < 8; j++) {
            int nl  = (j < 4) ? (tx * 4 + j) : (64 + tx * 4 + (j - 4));
            int col = nt * BN + nl;
            #pragma unroll
            for (int i = 0; i < 4; i++) {
                float v = acc[i][j];
                if (v > best_v[i]) { best_v[i] = v; best_i[i] = col; }
            }
        }
    }

    // Cross-thread reduction over tx (16 candidates per row), tie -> lower idx.
    __syncthreads();
    float* rv = Bs;                       // [64][16]
    int*   ri = (int*)(Bs + 64 * 16);     // [64][16]
    #pragma unroll
    for (int i = 0; i < 4; i++) {
        int row = ty * 4 + i;
        rv[row * 16 + tx] = best_v[i];
        ri[row * 16 + tx] = best_i[i];
    }
    __syncthreads();
    if (tid < BM) {
        float bv = -FLT_MAX;
        int   bi = S;
        #pragma unroll
        for (int t = 0; t < 16; t++) {
            float v = rv[tid * 16 + t];
            int  ix = ri[tid * 16 + t];
            if (v > bv || (v == bv && ix < bi)) { bv = v; bi = ix; }
        }
        int b = bm0 + tid;
        g_idx[b] = bi;
        atomicMax(&g_winner[bi], b);   // last-write-wins == max b
    }
}

// ---------------------------------------------------------------------------
// Kernel D: read_out[b] = vals[idx[b]]   (pre-update vals; vals never mutated)
// ---------------------------------------------------------------------------
__global__ void gather_kernel(const float* __restrict__ vals,
                              float* __restrict__ out, int D) {
    int b  = blockIdx.x * 4 + (threadIdx.x >> 6);
    int c4 = threadIdx.x & 63;           // D/4 = 64 float4 per row
    int idx = g_idx[b];
    float4 v = ((const float4*)(vals + (size_t)idx * D))[c4];
    ((float4*)(out + (size_t)b * D))[c4] = v;
}

// ---------------------------------------------------------------------------
// Kernel E: gated scatter update into new_keys / new_vals output sections.
// One block per slot s, 256 threads = D.
// ---------------------------------------------------------------------------
__global__ void update_kernel(const float* __restrict__ q,
                              const float* __restrict__ tgt,
                              const float* __restrict__ sur,
                              const float* __restrict__ keys,
                              const float* __restrict__ vals,
                              float* __restrict__ outK,
                              float* __restrict__ outV, int D) {
    int s = blockIdx.x;
    int d = threadIdx.x;
    int b = g_winner[s];
    float k = keys[(size_t)s * D + d];
    float v = vals[(size_t)s * D + d];
    if (b >= 0) {
        float g  = (1.0f / (1.0f + expf(-4.0f * sur[b]))) * LR;
        float om = 1.0f - g;
        outK[(size_t)s * D + d] = om * k + g * q[(size_t)b * D + d];
        outV[(size_t)s * D + d] = om * v + g * tgt[(size_t)b * D + d];
    } else {
        outK[(size_t)s * D + d] = k;
        outV[(size_t)s * D + d] = v;
    }
}

// ---------------------------------------------------------------------------
extern "C" void kernel_launch(void* const* d_in, const int* in_sizes, int n_in,
                              void* d_out, int out_size) {
    const float* query    = (const float*)d_in[0];
    const float* target   = (const float*)d_in[1];
    const float* surprise = (const float*)d_in[2];
    const float* keys     = (const float*)d_in[3];
    const float* vals     = (const float*)d_in[4];

    const int B = in_sizes[2];               // surprise is [B,1]
    const int D = in_sizes[0] / B;           // 256
    const int S = in_sizes[3] / D;           // 1024

    float* out      = (float*)d_out;
    float* out_read = out;
    float* out_keys = out + (size_t)B * D;
    float* out_vals = out + (size_t)(B + S) * D;

    // A: normalize keys + init winners
    knorm_kernel<<<S, 256>>>(keys, S, D);

    // B: fused GEMM + argmax
    const int smem_bytes = (DD * AST + BK * BN) * (int)sizeof(float);
    cudaFuncSetAttribute(score_argmax_kernel,
                         cudaFuncAttributeMaxDynamicSharedMemorySize, smem_bytes);
    score_argmax_kernel<<<B / BM, 256, smem_bytes>>>(query, B, S, D);

    // D: gather read_out
    gather_kernel<<<B / 4, 256>>>(vals, out_read, D);

    // E: gated scatter into new_keys / new_vals
    update_kernel<<<S, 256>>>(query, target, surprise, keys, vals,
                              out_keys, out_vals, D);
}

// round 3
// speedup vs baseline: 1.7309x; 1.7309x over previous
#include <cuda_runtime.h>
#include <math.h>
#include <float.h>
#include <stdint.h>

#define EPS 1e-8f
#define LR  0.1f

#define MAXB 131072
#define MAXS 1024
#define DD   256

// Global scratch (no cudaMalloc allowed)
__device__ float g_qhi[(size_t)MAXB * DD];
__device__ float g_qlo[(size_t)MAXB * DD];
__device__ float g_khi[(size_t)MAXS * DD];
__device__ float g_klo[(size_t)MAXS * DD];
__device__ int   g_idx[MAXB];
__device__ int   g_winner[MAXS];

// ---------------------------------------------------------------------------
// helpers
// ---------------------------------------------------------------------------
__device__ __forceinline__ uint32_t smem_u32(const void* p) {
    uint32_t a;
    asm("{ .reg .u64 t; cvta.to.shared.u64 t, %1; cvt.u32.u64 %0, t; }" : "=r"(a) : "l"(p));
    return a;
}
__device__ __forceinline__ float tf32r(float a) {
    uint32_t u;
    asm("cvt.rna.tf32.f32 %0, %1;" : "=r"(u) : "f"(a));
    return __uint_as_float(u);
}
__device__ __forceinline__ void cpasync16(uint32_t saddr, const void* gaddr) {
    asm volatile("cp.async.cg.shared.global [%0], [%1], 16;" :: "r"(saddr), "l"(gaddr));
}
#define CP_COMMIT()  asm volatile("cp.async.commit_group;" ::: "memory")
#define CP_WAIT(n)   asm volatile("cp.async.wait_group %0;" :: "n"(n) : "memory")

__device__ __forceinline__ void mma168(float* c, const uint32_t* a, const uint32_t* b) {
    asm volatile(
        "mma.sync.aligned.m16n8k8.row.col.f32.tf32.tf32.f32 "
        "{%0,%1,%2,%3}, {%4,%5,%6,%7}, {%8,%9}, {%0,%1,%2,%3};"
        : "+f"(c[0]), "+f"(c[1]), "+f"(c[2]), "+f"(c[3])
        : "r"(a[0]), "r"(a[1]), "r"(a[2]), "r"(a[3]), "r"(b[0]), "r"(b[1]));
}

// ---------------------------------------------------------------------------
// Prep 1: split queries into tf32 hi/lo  (one float4 per thread)
// ---------------------------------------------------------------------------
__global__ void qsplit_kernel(const float* __restrict__ q) {
    size_t i = (size_t)blockIdx.x * 256 + threadIdx.x;
    float4 v = ((const float4*)q)[i];
    float4 h, l;
    h.x = tf32r(v.x); h.y = tf32r(v.y); h.z = tf32r(v.z); h.w = tf32r(v.w);
    l.x = tf32r(v.x - h.x); l.y = tf32r(v.y - h.y);
    l.z = tf32r(v.z - h.z); l.w = tf32r(v.w - h.w);
    ((float4*)g_qhi)[i] = h;
    ((float4*)g_qlo)[i] = l;
}

// ---------------------------------------------------------------------------
// Prep 2: normalize keys -> tf32 hi/lo, init winner = -1
// ---------------------------------------------------------------------------
__global__ void knorm_kernel(const float* __restrict__ keys, int S, int D) {
    int s = blockIdx.x;
    int t = threadIdx.x;
    __shared__ float red[8];
    __shared__ float s_nrm;
    float v = keys[(size_t)s * D + t];
    float sq = v * v;
    #pragma unroll
    for (int o = 16; o; o >>= 1) sq += __shfl_xor_sync(0xFFFFFFFFu, sq, o);
    if ((t & 31) == 0) red[t >> 5] = sq;
    __syncthreads();
    if (t == 0) {
        float tot = 0.0f;
        #pragma unroll
        for (int i = 0; i < 8; i++) tot += red[i];
        s_nrm = fmaxf(sqrtf(tot), EPS);
        g_winner[s] = -1;
    }
    __syncthreads();
    float kn = v / s_nrm;
    float h  = tf32r(kn);
    g_khi[(size_t)s * D + t] = h;
    g_klo[(size_t)s * D + t] = tf32r(kn - h);
}

// ---------------------------------------------------------------------------
// Kernel B: mma.sync TF32 3-pass GEMM + argmax.
// CTA: 64 query rows, 256 threads (8 warps: 2 M-groups x 4 N-groups).
// A (hi/lo) resident in smem; B streamed in [128 x 32] hi/lo chunks (cp.async,
// double buffered). 64 chunks = 8 n-tiles x 8 k-chunks.
// ---------------------------------------------------------------------------
#define AST 260                 // padded A row stride (floats)
#define BST 36                  // padded B row stride (floats)
#define SM_AH 0
#define SM_AL (SM_AH + 64 * AST * 4)              // 66560
#define SM_BH (SM_AL + 64 * AST * 4)              // 133120
#define SM_BL (SM_BH + 2 * 128 * BST * 4)         // 169984
#define SM_TOTAL (SM_BL + 2 * 128 * BST * 4)      // 206848
#define BBUF (128 * BST * 4)                      // 18432

__global__ void __launch_bounds__(256, 1)
score_argmax_kernel(int B, int S) {
    extern __shared__ char sm[];
    const uint32_t smb = smem_u32(sm);
    const int tid  = threadIdx.x;
    const int wid  = tid >> 5;
    const int lane = tid & 31;
    const int wM   = wid >> 2;       // 0..1
    const int wN   = wid & 3;        // 0..3
    const int qrow = lane >> 2;      // 0..7
    const int qk   = lane & 3;       // 0..3
    const int bm0  = blockIdx.x * 64;

    float* Ah = (float*)(sm + SM_AH);
    float* Al = (float*)(sm + SM_AL);

    // ---- load A tile (64 x 256 hi/lo) into smem, padded stride ----
    #pragma unroll
    for (int i = 0; i < 16; i++) {
        int idx = tid + i * 256;          // 0..4095
        int r  = idx >> 6;
        int c4 = idx & 63;
        size_t g = (size_t)(bm0 + r) * DD + c4 * 4;
        *(float4*)&Ah[r * AST + c4 * 4] = *(const float4*)&g_qhi[g];
        *(float4*)&Al[r * AST + c4 * 4] = *(const float4*)&g_qlo[g];
    }

    // ---- cp.async issue helper (chunk c -> buffer c&1) ----
    const int n_chunks = (S / 128) * 8;
    auto issueB = [&](int c) {
        int nt = c >> 3, kc = c & 7, buf = c & 1;
        #pragma unroll
        for (int i = 0; i < 4; i++) {
            int s   = tid + i * 256;          // 0..1023
            int row = s >> 3, seg = s & 7;
            size_t g = (size_t)(nt * 128 + row) * DD + kc * 32 + seg * 4;
            uint32_t so = (uint32_t)(row * BST + seg * 4) * 4;
            cpasync16(smb + SM_BH + buf * BBUF + so, &g_khi[g]);
            cpasync16(smb + SM_BL + buf * BBUF + so, &g_klo[g]);
        }
        CP_COMMIT();
    };

    issueB(0);

    float acc[2][4][4];
    float bv[4];
    int   bi[4];
    #pragma unroll
    for (int r = 0; r < 4; r++) { bv[r] = -FLT_MAX; bi[r] = 0; }

    for (int c = 0; c < n_chunks; c++) {
        const int nt = c >> 3, kc = c & 7, buf = c & 1;
        if (c + 1 < n_chunks) issueB(c + 1);
        if (c + 1 < n_chunks) { CP_WAIT(1); } else { CP_WAIT(0); }
        __syncthreads();

        if (kc == 0) {
            #pragma unroll
            for (int mt = 0; mt < 2; mt++)
                #pragma unroll
                for (int j = 0; j < 4; j++)
                    #pragma unroll
                    for (int e = 0; e < 4; e++) acc[mt][j][e] = 0.0f;
        }

        const float* Bh = (const float*)(sm + SM_BH + buf * BBUF);
        const float* Bl = (const float*)(sm + SM_BL + buf * BBUF);

        #pragma unroll
        for (int ks = 0; ks < 4; ks++) {
            const int k = kc * 32 + ks * 8 + qk;
            uint32_t ah[2][4], al[2][4];
            #pragma unroll
            for (int mt = 0; mt < 2; mt++) {
                int base = (wM * 32 + mt * 16 + qrow) * AST + k;
                ah[mt][0] = __float_as_uint(Ah[base]);
                ah[mt][1] = __float_as_uint(Ah[base + 8 * AST]);
                ah[mt][2] = __float_as_uint(Ah[base + 4]);
                ah[mt][3] = __float_as_uint(Ah[base + 8 * AST + 4]);
                al[mt][0] = __float_as_uint(Al[base]);
                al[mt][1] = __float_as_uint(Al[base + 8 * AST]);
                al[mt][2] = __float_as_uint(Al[base + 4]);
                al[mt][3] = __float_as_uint(Al[base + 8 * AST + 4]);
            }
            #pragma unroll
            for (int j = 0; j < 4; j++) {
                int bb = (wN * 32 + j * 8 + qrow) * BST + ks * 8 + qk;
                uint32_t bh[2] = { __float_as_uint(Bh[bb]), __float_as_uint(Bh[bb + 4]) };
                uint32_t bl[2] = { __float_as_uint(Bl[bb]), __float_as_uint(Bl[bb + 4]) };
                #pragma unroll
                for (int mt = 0; mt < 2; mt++) {
                    mma168(acc[mt][j], ah[mt], bh);
                    mma168(acc[mt][j], ah[mt], bl);
                    mma168(acc[mt][j], al[mt], bh);
                }
            }
        }

        if (kc == 7) {
            // running argmax over this n-tile (cols ascending => strict > keeps lowest)
            #pragma unroll
            for (int j = 0; j < 4; j++) {
                int col0 = nt * 128 + wN * 32 + j * 8 + 2 * qk;
                #pragma unroll
                for (int mt = 0; mt < 2; mt++)
                    #pragma unroll
                    for (int rr = 0; rr < 2; rr++) {
                        int r = mt * 2 + rr;
                        float v0 = acc[mt][j][rr * 2 + 0];
                        float v1 = acc[mt][j][rr * 2 + 1];
                        if (v0 > bv[r]) { bv[r] = v0; bi[r] = col0; }
                        if (v1 > bv[r]) { bv[r] = v1; bi[r] = col0 + 1; }
                    }
            }
        }
        __syncthreads();   // protect buffer reuse by next issue
    }

    // ---- quad reduce (lanes in a quad share rows, differ in cols) ----
    #pragma unroll
    for (int off = 1; off <= 2; off <<= 1) {
        #pragma unroll
        for (int r = 0; r < 4; r++) {
            float ov = __shfl_xor_sync(0xFFFFFFFFu, bv[r], off);
            int   oi = __shfl_xor_sync(0xFFFFFFFFu, bi[r], off);
            if (ov > bv[r] || (ov == bv[r] && oi < bi[r])) { bv[r] = ov; bi[r] = oi; }
        }
    }

    // ---- cross-warp (warpN) reduce via smem ----
    float* rv = (float*)(sm + SM_BH);            // [64][4]
    int*   ri = (int*)(sm + SM_BH + 64 * 4 * 4); // [64][4]
    if ((lane & 3) == 0) {
        #pragma unroll
        for (int r = 0; r < 4; r++) {
            int mt = r >> 1, rr = r & 1;
            int row = wM * 32 + mt * 16 + qrow + 8 * rr;
            rv[row * 4 + wN] = bv[r];
            ri[row * 4 + wN] = bi[r];
        }
    }
    __syncthreads();
    if (tid < 64) {
        float fv = -FLT_MAX;
        int   fi = S;
        #pragma unroll
        for (int t = 0; t < 4; t++) {
            float v = rv[tid * 4 + t];
            int   x = ri[tid * 4 + t];
            if (v > fv || (v == fv && x < fi)) { fv = v; fi = x; }
        }
        int b = bm0 + tid;
        g_idx[b] = fi;
        atomicMax(&g_winner[fi], b);
    }
}

// ---------------------------------------------------------------------------
// Kernel D: read_out[b] = vals[idx[b]]
// ---------------------------------------------------------------------------
__global__ void gather_kernel(const float* __restrict__ vals,
                              float* __restrict__ out, int D) {
    int b  = blockIdx.x * 4 + (threadIdx.x >> 6);
    int c4 = threadIdx.x & 63;
    int idx = g_idx[b];
    float4 v = ((const float4*)(vals + (size_t)idx * D))[c4];
    ((float4*)(out + (size_t)b * D))[c4] = v;
}

// ---------------------------------------------------------------------------
// Kernel E: gated scatter update
// ---------------------------------------------------------------------------
__global__ void update_kernel(const float* __restrict__ q,
                              const float* __restrict__ tgt,
                              const float* __restrict__ sur,
                              const float* __restrict__ keys,
                              const float* __restrict__ vals,
                              float* __restrict__ outK,
                              float* __restrict__ outV, int D) {
    int s = blockIdx.x;
    int d = threadIdx.x;
    int b = g_winner[s];
    float k = keys[(size_t)s * D + d];
    float v = vals[(size_t)s * D + d];
    if (b >= 0) {
        float g  = (1.0f / (1.0f + expf(-4.0f * sur[b]))) * LR;
        float om = 1.0f - g;
        outK[(size_t)s * D + d] = om * k + g * q[(size_t)b * D + d];
        outV[(size_t)s * D + d] = om * v + g * tgt[(size_t)b * D + d];
    } else {
        outK[(size_t)s * D + d] = k;
        outV[(size_t)s * D + d] = v;
    }
}

// ---------------------------------------------------------------------------
extern "C" void kernel_launch(void* const* d_in, const int* in_sizes, int n_in,
                              void* d_out, int out_size) {
    const float* query    = (const float*)d_in[0];
    const float* target   = (const float*)d_in[1];
    const float* surprise = (const float*)d_in[2];
    const float* keys     = (const float*)d_in[3];
    const float* vals     = (const float*)d_in[4];

    const int B = in_sizes[2];
    const int D = in_sizes[0] / B;     // 256
    const int S = in_sizes[3] / D;     // 1024

    float* out      = (float*)d_out;
    float* out_read = out;
    float* out_keys = out + (size_t)B * D;
    float* out_vals = out + (size_t)(B + S) * D;

    qsplit_kernel<<<(B * D) / 1024, 256>>>(query);
    knorm_kernel<<<S, 256>>>(keys, S, D);

    cudaFuncSetAttribute(score_argmax_kernel,
                         cudaFuncAttributeMaxDynamicSharedMemorySize, SM_TOTAL);
    score_argmax_kernel<<<B / 64, 256, SM_TOTAL>>>(B, S);

    gather_kernel<<<B / 4, 256>>>(vals, out_read, D);

    update_kernel<<<S, 256>>>(query, target, surprise, keys, vals,
                              out_keys, out_vals, D);
}

// round 4
// speedup vs baseline: 3.4562x; 1.9967x over previous
#include <cuda_runtime.h>
#include <math.h>
#include <float.h>
#include <stdint.h>

#define EPS 1e-8f
#define LR  0.1f
#define THRESH 8e-3f

#define MAXB 131072
#define MAXS 1024
#define DD   256

// Global scratch
__device__ float g_kn [(size_t)MAXS * DD];   // normalized keys fp32 (rescore)
__device__ float g_khi[(size_t)MAXS * DD];   // tf32-rounded normalized keys
__device__ int   g_idx[MAXB];
__device__ int   g_winner[MAXS];
__device__ int   g_flagged[MAXB];
__device__ int   g_nflag;

// ---------------------------------------------------------------------------
__device__ __forceinline__ uint32_t smem_u32(const void* p) {
    uint32_t a;
    asm("{ .reg .u64 t; cvta.to.shared.u64 t, %1; cvt.u32.u64 %0, t; }" : "=r"(a) : "l"(p));
    return a;
}
__device__ __forceinline__ float tf32r(float a) {
    uint32_t u;
    asm("cvt.rna.tf32.f32 %0, %1;" : "=r"(u) : "f"(a));
    return __uint_as_float(u);
}
__device__ __forceinline__ void cpasync16(uint32_t saddr, const void* gaddr) {
    asm volatile("cp.async.cg.shared.global [%0], [%1], 16;" :: "r"(saddr), "l"(gaddr));
}
#define CP_COMMIT()  asm volatile("cp.async.commit_group;" ::: "memory")
#define CP_WAIT(n)   asm volatile("cp.async.wait_group %0;" :: "n"(n) : "memory")

__device__ __forceinline__ void mma168(float* c, const uint32_t* a, const uint32_t* b) {
    asm volatile(
        "mma.sync.aligned.m16n8k8.row.col.f32.tf32.tf32.f32 "
        "{%0,%1,%2,%3}, {%4,%5,%6,%7}, {%8,%9}, {%0,%1,%2,%3};"
        : "+f"(c[0]), "+f"(c[1]), "+f"(c[2]), "+f"(c[3])
        : "r"(a[0]), "r"(a[1]), "r"(a[2]), "r"(a[3]), "r"(b[0]), "r"(b[1]));
}

// ---------------------------------------------------------------------------
// Prep: normalize keys -> fp32 + tf32 hi; init winner=-1, nflag=0
// ---------------------------------------------------------------------------
__global__ void knorm_kernel(const float* __restrict__ keys, int S, int D) {
    int s = blockIdx.x;
    int t = threadIdx.x;
    __shared__ float red[8];
    __shared__ float s_nrm;
    float v = keys[(size_t)s * D + t];
    float sq = v * v;
    #pragma unroll
    for (int o = 16; o; o >>= 1) sq += __shfl_xor_sync(0xFFFFFFFFu, sq, o);
    if ((t & 31) == 0) red[t >> 5] = sq;
    __syncthreads();
    if (t == 0) {
        float tot = 0.0f;
        #pragma unroll
        for (int i = 0; i < 8; i++) tot += red[i];
        s_nrm = fmaxf(sqrtf(tot), EPS);
        g_winner[s] = -1;
        if (s == 0) g_nflag = 0;
    }
    __syncthreads();
    float kn = v / s_nrm;
    g_kn [(size_t)s * D + t] = kn;
    g_khi[(size_t)s * D + t] = tf32r(kn);
}

// ---------------------------------------------------------------------------
// Stage 1: single-pass tf32 GEMM + argmax + 2nd-max gap filter.
// CTA: 128 query rows, 256 threads = 8 warps (wM=wid>>1 in 0..3, wN=wid&1).
// A stored in smem in MMA FRAGMENT ORDER: Afr[m16t][k8t][lane][4] -> LDS.128.
// B: [128 keys x 32 K] tf32-hi chunks, cp.async double-buffered.
// ---------------------------------------------------------------------------
#define BST 36
#define BBUF (128 * BST * 4)                 // 18432 B
#define SM_AFR 0                             // 8*32*32*4 floats = 131072 B
#define SM_B   131072
#define SM_TOTAL (SM_B + 2 * BBUF)           // 167936 B
// reduce scratch (after last B use): rv/ri/rv2 each 128*2
#define RED_V  (SM_B)
#define RED_I  (SM_B + 128*2*4)
#define RED_V2 (SM_B + 128*2*4*2)

__global__ void __launch_bounds__(256, 1)
score_argmax_kernel(const float* __restrict__ q, int B, int S) {
    extern __shared__ char sm[];
    const uint32_t smb = smem_u32(sm);
    float* Afr = (float*)(sm + SM_AFR);
    const int tid  = threadIdx.x;
    const int wid  = tid >> 5;
    const int lane = tid & 31;
    const int wM   = wid >> 1;        // 0..3
    const int wN   = wid & 1;         // 0..1
    const int qrow = lane >> 2;       // 0..7
    const int qk   = lane & 3;        // 0..3
    const int bm0  = blockIdx.x * 128;

    // ---- A load: 128x256, tf32-round, store in fragment order ----
    {
        const float* qb = q + (size_t)bm0 * DD;
        #pragma unroll
        for (int i = tid; i < 128 * 64; i += 256) {
            int r  = i >> 6;
            int c4 = (i & 63) * 4;
            float4 v = *(const float4*)(qb + (size_t)r * DD + c4);
            float h0 = tf32r(v.x), h1 = tf32r(v.y), h2 = tf32r(v.z), h3 = tf32r(v.w);
            int m16t  = r >> 4;
            int rr    = (r >> 3) & 1;
            int row8  = r & 7;
            int k8t   = c4 >> 3;
            int chalf = (c4 >> 2) & 1;
            int base  = (((m16t * 32 + k8t) * 32) + row8 * 4) * 4 + rr + 2 * chalf;
            Afr[base + 0] = h0;   // lane row8*4+0
            Afr[base + 4] = h1;
            Afr[base + 8] = h2;
            Afr[base + 12] = h3;
        }
    }

    const int n_chunks = (S / 128) * 8;
    auto issueB = [&](int c) {
        int nt = c >> 3, kc = c & 7, buf = c & 1;
        #pragma unroll
        for (int i = 0; i < 4; i++) {
            int s   = tid + i * 256;
            int row = s >> 3, seg = s & 7;
            size_t g = (size_t)(nt * 128 + row) * DD + kc * 32 + seg * 4;
            uint32_t so = (uint32_t)(row * BST + seg * 4) * 4;
            cpasync16(smb + SM_B + buf * BBUF + so, &g_khi[g]);
        }
        CP_COMMIT();
    };

    issueB(0);

    float acc[2][8][4];
    float bv[4], bv2[4];
    int   bi[4];
    #pragma unroll
    for (int r = 0; r < 4; r++) { bv[r] = -FLT_MAX; bv2[r] = -FLT_MAX; bi[r] = 0; }

    for (int c = 0; c < n_chunks; c++) {
        const int nt = c >> 3, kc = c & 7, buf = c & 1;
        if (c + 1 < n_chunks) { issueB(c + 1); CP_WAIT(1); } else { CP_WAIT(0); }
        __syncthreads();

        if (kc == 0) {
            #pragma unroll
            for (int mt = 0; mt < 2; mt++)
                #pragma unroll
                for (int j = 0; j < 8; j++)
                    #pragma unroll
                    for (int e = 0; e < 4; e++) acc[mt][j][e] = 0.0f;
        }

        const float* Bh = (const float*)(sm + SM_B + buf * BBUF);

        #pragma unroll
        for (int ks = 0; ks < 4; ks++) {
            const int k8t = kc * 4 + ks;
            float4 af[2];
            #pragma unroll
            for (int mt = 0; mt < 2; mt++) {
                int m16t = wM * 2 + mt;
                af[mt] = *(const float4*)&Afr[(((m16t * 32 + k8t) * 32) + lane) * 4];
            }
            #pragma unroll
            for (int j = 0; j < 8; j++) {
                int bb = (wN * 64 + j * 8 + qrow) * BST + ks * 8 + qk;
                uint32_t b[2] = { __float_as_uint(Bh[bb]), __float_as_uint(Bh[bb + 4]) };
                mma168(acc[0][j], (const uint32_t*)&af[0], b);
                mma168(acc[1][j], (const uint32_t*)&af[1], b);
            }
        }

        if (kc == 7) {
            #pragma unroll
            for (int j = 0; j < 8; j++) {
                int col0 = nt * 128 + wN * 64 + j * 8 + 2 * qk;
                #pragma unroll
                for (int mt = 0; mt < 2; mt++)
                    #pragma unroll
                    for (int rr = 0; rr < 2; rr++) {
                        int r = mt * 2 + rr;
                        float v0 = acc[mt][j][rr * 2 + 0];
                        float v1 = acc[mt][j][rr * 2 + 1];
                        if (v0 > bv[r]) { bv2[r] = bv[r]; bv[r] = v0; bi[r] = col0; }
                        else            { bv2[r] = fmaxf(bv2[r], v0); }
                        if (v1 > bv[r]) { bv2[r] = bv[r]; bv[r] = v1; bi[r] = col0 + 1; }
                        else            { bv2[r] = fmaxf(bv2[r], v1); }
                    }
            }
        }
        __syncthreads();
    }

    // ---- quad reduce (lanes in a quad share rows) ----
    #pragma unroll
    for (int off = 1; off <= 2; off <<= 1) {
        #pragma unroll
        for (int r = 0; r < 4; r++) {
            float ov  = __shfl_xor_sync(0xFFFFFFFFu, bv[r],  off);
            int   oi  = __shfl_xor_sync(0xFFFFFFFFu, bi[r],  off);
            float ov2 = __shfl_xor_sync(0xFFFFFFFFu, bv2[r], off);
            if (ov > bv[r]) { bv2[r] = fmaxf(bv[r], ov2); bv[r] = ov; bi[r] = oi; }
            else {
                if (ov == bv[r] && oi < bi[r]) bi[r] = oi;
                bv2[r] = fmaxf(bv2[r], ov);
            }
        }
    }

    // ---- cross-warp (wN) reduce via smem ----
    float* rv  = (float*)(sm + RED_V);
    int*   ri  = (int*)  (sm + RED_I);
    float* rv2 = (float*)(sm + RED_V2);
    if (qk == 0) {
        #pragma unroll
        for (int r = 0; r < 4; r++) {
            int mt = r >> 1, rr = r & 1;
            int row = wM * 32 + mt * 16 + rr * 8 + qrow;
            rv [row * 2 + wN] = bv[r];
            ri [row * 2 + wN] = bi[r];
            rv2[row * 2 + wN] = bv2[r];
        }
    }
    __syncthreads();
    if (tid < 128) {
        float fv = rv[tid * 2], fv2 = rv2[tid * 2];
        int   fi = ri[tid * 2];
        float ov = rv[tid * 2 + 1], ov2 = rv2[tid * 2 + 1];
        int   oi = ri[tid * 2 + 1];
        if (ov > fv) { fv2 = fmaxf(fv, ov2); fv = ov; fi = oi; }
        else {
            if (ov == fv && oi < fi) fi = oi;
            fv2 = fmaxf(fv2, ov);
        }
        int b = bm0 + tid;
        g_idx[b] = fi;
        if (fv - fv2 < THRESH) {
            int p = atomicAdd(&g_nflag, 1);
            g_flagged[p] = b;
        }
    }
}

// ---------------------------------------------------------------------------
// Stage 2: exact fp32 rescore of flagged rows against all S keys.
// 16 rows per block iteration; each thread handles 4 keys.
// ---------------------------------------------------------------------------
__global__ void __launch_bounds__(256)
rescore_kernel(const float* __restrict__ q, int S) {
    __shared__ float sq[16 * 256];
    __shared__ float rv[16][8];
    __shared__ int   rix[16][8];
    const int tid  = threadIdx.x;
    const int wid  = tid >> 5;
    const int lane = tid & 31;
    const int nf = g_nflag;

    for (int base = blockIdx.x * 16; base < nf; base += gridDim.x * 16) {
        int nr = min(16, nf - base);
        for (int i = tid; i < nr * 256; i += 256) {
            int r = i >> 8, d = i & 255;
            sq[r * 256 + d] = q[(size_t)g_flagged[base + r] * 256 + d];
        }
        __syncthreads();

        float bvl[16]; int bil[16];
        #pragma unroll
        for (int r = 0; r < 16; r++) { bvl[r] = -FLT_MAX; bil[r] = 0; }

        for (int kq = 0; kq < 4; kq++) {
            int s = kq * 256 + tid;
            float acc[16];
            #pragma unroll
            for (int r = 0; r < 16; r++) acc[r] = 0.0f;
            const float4* kr = (const float4*)(g_kn + (size_t)s * 256);
            for (int d4 = 0; d4 < 64; d4++) {
                float4 kv = kr[d4];
                #pragma unroll
                for (int r = 0; r < 16; r++) {
                    const float4 qv = *(const float4*)&sq[r * 256 + d4 * 4];
                    acc[r] = fmaf(qv.x, kv.x, acc[r]);
                    acc[r] = fmaf(qv.y, kv.y, acc[r]);
                    acc[r] = fmaf(qv.z, kv.z, acc[r]);
                    acc[r] = fmaf(qv.w, kv.w, acc[r]);
                }
            }
            #pragma unroll
            for (int r = 0; r < 16; r++)
                if (acc[r] > bvl[r]) { bvl[r] = acc[r]; bil[r] = s; }
        }

        // warp reduce
        #pragma unroll
        for (int off = 16; off; off >>= 1) {
            #pragma unroll
            for (int r = 0; r < 16; r++) {
                float ov = __shfl_xor_sync(0xFFFFFFFFu, bvl[r], off);
                int   oi = __shfl_xor_sync(0xFFFFFFFFu, bil[r], off);
                if (ov > bvl[r] || (ov == bvl[r] && oi < bil[r])) { bvl[r] = ov; bil[r] = oi; }
            }
        }
        if (lane == 0) {
            #pragma unroll
            for (int r = 0; r < 16; r++) { rv[r][wid] = bvl[r]; rix[r][wid] = bil[r]; }
        }
        __syncthreads();
        if (tid < nr) {
            float fv = -FLT_MAX; int fi = S;
            #pragma unroll
            for (int w = 0; w < 8; w++) {
                float v = rv[tid][w]; int i = rix[tid][w];
                if (v > fv || (v == fv && i < fi)) { fv = v; fi = i; }
            }
            g_idx[g_flagged[base + tid]] = fi;
        }
        __syncthreads();
    }
}

// ---------------------------------------------------------------------------
// Gather read_out + winner vote (runs after rescore => final idx)
// ---------------------------------------------------------------------------
__global__ void gather_kernel(const float* __restrict__ vals,
                              float* __restrict__ out, int D) {
    int b  = blockIdx.x * 4 + (threadIdx.x >> 6);
    int c4 = threadIdx.x & 63;
    int idx = g_idx[b];
    float4 v = ((const float4*)(vals + (size_t)idx * D))[c4];
    ((float4*)(out + (size_t)b * D))[c4] = v;
    if (c4 == 0) atomicMax(&g_winner[idx], b);
}

// ---------------------------------------------------------------------------
// Gated scatter update
// ---------------------------------------------------------------------------
__global__ void update_kernel(const float* __restrict__ q,
                              const float* __restrict__ tgt,
                              const float* __restrict__ sur,
                              const float* __restrict__ keys,
                              const float* __restrict__ vals,
                              float* __restrict__ outK,
                              float* __restrict__ outV, int D) {
    int s = blockIdx.x;
    int d = threadIdx.x;
    int b = g_winner[s];
    float k = keys[(size_t)s * D + d];
    float v = vals[(size_t)s * D + d];
    if (b >= 0) {
        float g  = (1.0f / (1.0f + expf(-4.0f * sur[b]))) * LR;
        float om = 1.0f - g;
        outK[(size_t)s * D + d] = om * k + g * q[(size_t)b * D + d];
        outV[(size_t)s * D + d] = om * v + g * tgt[(size_t)b * D + d];
    } else {
        outK[(size_t)s * D + d] = k;
        outV[(size_t)s * D + d] = v;
    }
}

// ---------------------------------------------------------------------------
extern "C" void kernel_launch(void* const* d_in, const int* in_sizes, int n_in,
                              void* d_out, int out_size) {
    const float* query    = (const float*)d_in[0];
    const float* target   = (const float*)d_in[1];
    const float* surprise = (const float*)d_in[2];
    const float* keys     = (const float*)d_in[3];
    const float* vals     = (const float*)d_in[4];

    const int B = in_sizes[2];
    const int D = in_sizes[0] / B;     // 256
    const int S = in_sizes[3] / D;     // 1024

    float* out      = (float*)d_out;
    float* out_read = out;
    float* out_keys = out + (size_t)B * D;
    float* out_vals = out + (size_t)(B + S) * D;

    knorm_kernel<<<S, 256>>>(keys, S, D);

    cudaFuncSetAttribute(score_argmax_kernel,
                         cudaFuncAttributeMaxDynamicSharedMemorySize, SM_TOTAL);
    score_argmax_kernel<<<B / 128, 256, SM_TOTAL>>>(query, B, S);

    rescore_kernel<<<1024, 256>>>(query, S);

    gather_kernel<<<B / 4, 256>>>(vals, out_read, D);

    update_kernel<<<S, 256>>>(query, target, surprise, keys, vals,
                              out_keys, out_vals, D);
}

// round 5
// speedup vs baseline: 6.2689x; 1.8138x over previous
#include <cuda_runtime.h>
#include <cuda_fp16.h>
#include <math.h>
#include <float.h>
#include <stdint.h>

#define EPS 1e-8f
#define LR  0.1f
#define THRESH 8e-3f

#define MAXB 131072
#define MAXS 1024
#define DD   256

// Global scratch
__device__ float  g_kn[(size_t)MAXS * DD];    // normalized keys fp32 (rescore)
__device__ __half g_kh[(size_t)MAXS * DD];    // normalized keys fp16 (GEMM)
__device__ int    g_idx[MAXB];
__device__ int    g_winner[MAXS];
__device__ int    g_flagged[MAXB];
__device__ int    g_nflag;

// ---------------------------------------------------------------------------
__device__ __forceinline__ uint32_t smem_u32(const void* p) {
    uint32_t a;
    asm("{ .reg .u64 t; cvta.to.shared.u64 t, %1; cvt.u32.u64 %0, t; }" : "=r"(a) : "l"(p));
    return a;
}
__device__ __forceinline__ void cpasync16(uint32_t saddr, const void* gaddr) {
    asm volatile("cp.async.cg.shared.global [%0], [%1], 16;" :: "r"(saddr), "l"(gaddr));
}
#define CP_COMMIT()  asm volatile("cp.async.commit_group;" ::: "memory")
#define CP_WAIT(n)   asm volatile("cp.async.wait_group %0;" :: "n"(n) : "memory")

__device__ __forceinline__ void ldm4(uint32_t* d, uint32_t addr) {
    asm volatile("ldmatrix.sync.aligned.m8n8.x4.shared.b16 {%0,%1,%2,%3}, [%4];"
        : "=r"(d[0]), "=r"(d[1]), "=r"(d[2]), "=r"(d[3]) : "r"(addr));
}
__device__ __forceinline__ void mma16816(float* c, const uint32_t* a, const uint32_t* b) {
    asm volatile(
        "mma.sync.aligned.m16n8k16.row.col.f32.f16.f16.f32 "
        "{%0,%1,%2,%3}, {%4,%5,%6,%7}, {%8,%9}, {%0,%1,%2,%3};"
        : "+f"(c[0]), "+f"(c[1]), "+f"(c[2]), "+f"(c[3])
        : "r"(a[0]), "r"(a[1]), "r"(a[2]), "r"(a[3]), "r"(b[0]), "r"(b[1]));
}

// ---------------------------------------------------------------------------
// Prep: normalize keys -> fp32 + fp16; init winner=-1, nflag=0
// ---------------------------------------------------------------------------
__global__ void knorm_kernel(const float* __restrict__ keys, int S, int D) {
    int s = blockIdx.x;
    int t = threadIdx.x;
    __shared__ float red[8];
    __shared__ float s_nrm;
    float v = keys[(size_t)s * D + t];
    float sq = v * v;
    #pragma unroll
    for (int o = 16; o; o >>= 1) sq += __shfl_xor_sync(0xFFFFFFFFu, sq, o);
    if ((t & 31) == 0) red[t >> 5] = sq;
    __syncthreads();
    if (t == 0) {
        float tot = 0.0f;
        #pragma unroll
        for (int i = 0; i < 8; i++) tot += red[i];
        s_nrm = fmaxf(sqrtf(tot), EPS);
        g_winner[s] = -1;
        if (s == 0) g_nflag = 0;
    }
    __syncthreads();
    float kn = v / s_nrm;
    g_kn[(size_t)s * D + t] = kn;
    g_kh[(size_t)s * D + t] = __float2half_rn(kn);
}

// ---------------------------------------------------------------------------
// Stage 1: fp16 m16n8k16 GEMM + argmax + 2nd-max gap filter.
// CTA: 128 query rows, 256 threads, 8 warps = 4 wM x 2 wN.
// A: q tile converted to fp16 in smem, padded stride 264 halves (528 B, odd
//    16B-granule count => conflict-free ldmatrix). B: [128 keys x 64 K] fp16
//    chunks, cp.async double-buffered, stride 72 halves (144 B, odd granules).
// Chunks: nt 0..7 (128 keys) x kc 0..3 (K=64). 2 CTAs/SM.
// ---------------------------------------------------------------------------
#define ASTB 528                      // A row stride bytes
#define BSTB 144                      // B row stride bytes
#define SM_A   0
#define SM_B   (128 * ASTB)           // 67584
#define BBUF   (128 * BSTB)           // 18432
#define SM_TOTAL (SM_B + 2 * BBUF)    // 104448
#define RED_V  (SM_B)
#define RED_I  (SM_B + 128*2*4)
#define RED_V2 (SM_B + 128*2*4*2)

__global__ void __launch_bounds__(256, 2)
score_argmax_kernel(const float* __restrict__ q, int B, int S) {
    extern __shared__ char sm[];
    const uint32_t smb = smem_u32(sm);
    const int tid  = threadIdx.x;
    const int wid  = tid >> 5;
    const int lane = tid & 31;
    const int wM   = wid >> 1;        // 0..3
    const int wN   = wid & 1;         // 0..1
    const int qrow = lane >> 2;       // 0..7
    const int qk   = lane & 3;        // 0..3
    const int bm0  = blockIdx.x * 128;

    // ---- A: load q fp32, convert fp16, store padded row-major ----
    {
        const float* qb = q + (size_t)bm0 * DD;
        #pragma unroll
        for (int i = tid; i < 128 * 64; i += 256) {
            int r  = i >> 6;
            int c4 = (i & 63) * 4;
            float4 v = *(const float4*)(qb + (size_t)r * DD + c4);
            __half2 h0 = __floats2half2_rn(v.x, v.y);
            __half2 h1 = __floats2half2_rn(v.z, v.w);
            uint2 pk = { *(uint32_t*)&h0, *(uint32_t*)&h1 };
            *(uint2*)(sm + SM_A + r * ASTB + c4 * 2) = pk;
        }
    }

    // per-thread ldmatrix base addresses
    const uint32_t aBase = smb + SM_A +
        (uint32_t)((wM * 32 + ((lane >> 3) & 1) * 8 + (lane & 7)) * ASTB + (lane >> 4) * 16);
    const uint32_t bBase0 = smb + SM_B +
        (uint32_t)((wN * 64 + ((lane >> 4) & 1) * 8 + (lane & 7)) * BSTB + ((lane >> 3) & 1) * 16);

    const int n_chunks = (S / 128) * 4;
    auto issueB = [&](int c) {
        int nt = c >> 2, kc = c & 3, buf = c & 1;
        #pragma unroll
        for (int i = 0; i < 4; i++) {
            int s2  = tid + i * 256;
            int row = s2 >> 3, seg = s2 & 7;
            const __half* g = g_kh + (size_t)(nt * 128 + row) * DD + kc * 64 + seg * 8;
            cpasync16(smb + SM_B + buf * BBUF + (uint32_t)(row * BSTB + seg * 16), g);
        }
        CP_COMMIT();
    };

    issueB(0);

    float acc[2][8][4];
    float bv[4], bv2[4];
    int   bi[4];
    #pragma unroll
    for (int r = 0; r < 4; r++) { bv[r] = -FLT_MAX; bv2[r] = -FLT_MAX; bi[r] = 0; }

    for (int c = 0; c < n_chunks; c++) {
        const int nt = c >> 2, kc = c & 3, buf = c & 1;
        if (c + 1 < n_chunks) { issueB(c + 1); CP_WAIT(1); } else { CP_WAIT(0); }
        __syncthreads();

        if (kc == 0) {
            #pragma unroll
            for (int mt = 0; mt < 2; mt++)
                #pragma unroll
                for (int j = 0; j < 8; j++)
                    #pragma unroll
                    for (int e = 0; e < 4; e++) acc[mt][j][e] = 0.0f;
        }

        const uint32_t bBase = bBase0 + (uint32_t)buf * BBUF;

        #pragma unroll
        for (int ks = 0; ks < 4; ks++) {
            uint32_t a0[4], a1[4];
            ldm4(a0, aBase + (uint32_t)(kc * 128 + ks * 32));
            ldm4(a1, aBase + (uint32_t)(16 * ASTB + kc * 128 + ks * 32));
            #pragma unroll
            for (int jp = 0; jp < 4; jp++) {
                uint32_t bb[4];
                ldm4(bb, bBase + (uint32_t)(jp * (16 * BSTB) + ks * 32));
                mma16816(acc[0][jp * 2 + 0], a0, bb);
                mma16816(acc[0][jp * 2 + 1], a0, bb + 2);
                mma16816(acc[1][jp * 2 + 0], a1, bb);
                mma16816(acc[1][jp * 2 + 1], a1, bb + 2);
            }
        }

        if (kc == 3) {
            #pragma unroll
            for (int j = 0; j < 8; j++) {
                int col0 = nt * 128 + wN * 64 + j * 8 + 2 * qk;
                #pragma unroll
                for (int mt = 0; mt < 2; mt++)
                    #pragma unroll
                    for (int rr = 0; rr < 2; rr++) {
                        int r = mt * 2 + rr;
                        float v0 = acc[mt][j][rr * 2 + 0];
                        float v1 = acc[mt][j][rr * 2 + 1];
                        if (v0 > bv[r]) { bv2[r] = bv[r]; bv[r] = v0; bi[r] = col0; }
                        else            { bv2[r] = fmaxf(bv2[r], v0); }
                        if (v1 > bv[r]) { bv2[r] = bv[r]; bv[r] = v1; bi[r] = col0 + 1; }
                        else            { bv2[r] = fmaxf(bv2[r], v1); }
                    }
            }
        }
        __syncthreads();
    }

    // ---- quad reduce ----
    #pragma unroll
    for (int off = 1; off <= 2; off <<= 1) {
        #pragma unroll
        for (int r = 0; r < 4; r++) {
            float ov  = __shfl_xor_sync(0xFFFFFFFFu, bv[r],  off);
            int   oi  = __shfl_xor_sync(0xFFFFFFFFu, bi[r],  off);
            float ov2 = __shfl_xor_sync(0xFFFFFFFFu, bv2[r], off);
            if (ov > bv[r]) { bv2[r] = fmaxf(bv[r], ov2); bv[r] = ov; bi[r] = oi; }
            else {
                if (ov == bv[r] && oi < bi[r]) bi[r] = oi;
                bv2[r] = fmaxf(bv2[r], ov);
            }
        }
    }

    // ---- cross-warp (wN) reduce ----
    float* rv  = (float*)(sm + RED_V);
    int*   ri  = (int*)  (sm + RED_I);
    float* rv2 = (float*)(sm + RED_V2);
    if (qk == 0) {
        #pragma unroll
        for (int r = 0; r < 4; r++) {
            int mt = r >> 1, rr = r & 1;
            int row = wM * 32 + mt * 16 + rr * 8 + qrow;
            rv [row * 2 + wN] = bv[r];
            ri [row * 2 + wN] = bi[r];
            rv2[row * 2 + wN] = bv2[r];
        }
    }
    __syncthreads();
    if (tid < 128) {
        float fv = rv[tid * 2], fv2 = rv2[tid * 2];
        int   fi = ri[tid * 2];
        float ov = rv[tid * 2 + 1], ov2 = rv2[tid * 2 + 1];
        int   oi = ri[tid * 2 + 1];
        if (ov > fv) { fv2 = fmaxf(fv, ov2); fv = ov; fi = oi; }
        else {
            if (ov == fv && oi < fi) fi = oi;
            fv2 = fmaxf(fv2, ov);
        }
        int b = bm0 + tid;
        g_idx[b] = fi;
        if (fv - fv2 < THRESH) {
            int p = atomicAdd(&g_nflag, 1);
            g_flagged[p] = b;
        }
    }
}

// ---------------------------------------------------------------------------
// Stage 2: exact fp32 rescore of flagged rows.
// ---------------------------------------------------------------------------
__global__ void __launch_bounds__(256)
rescore_kernel(const float* __restrict__ q, int S) {
    __shared__ float sq[16 * 256];
    __shared__ float rv[16][8];
    __shared__ int   rix[16][8];
    const int tid  = threadIdx.x;
    const int wid  = tid >> 5;
    const int lane = tid & 31;
    const int nf = g_nflag;

    for (int base = blockIdx.x * 16; base < nf; base += gridDim.x * 16) {
        int nr = min(16, nf - base);
        for (int i = tid; i < nr * 256; i += 256) {
            int r = i >> 8, d = i & 255;
            sq[r * 256 + d] = q[(size_t)g_flagged[base + r] * 256 + d];
        }
        __syncthreads();

        float bvl[16]; int bil[16];
        #pragma unroll
        for (int r = 0; r < 16; r++) { bvl[r] = -FLT_MAX; bil[r] = 0; }

        for (int kq = 0; kq < 4; kq++) {
            int s = kq * 256 + tid;
            float acc[16];
            #pragma unroll
            for (int r = 0; r < 16; r++) acc[r] = 0.0f;
            const float4* kr = (const float4*)(g_kn + (size_t)s * 256);
            for (int d4 = 0; d4 < 64; d4++) {
                float4 kv = kr[d4];
                #pragma unroll
                for (int r = 0; r < 16; r++) {
                    const float4 qv = *(const float4*)&sq[r * 256 + d4 * 4];
                    acc[r] = fmaf(qv.x, kv.x, acc[r]);
                    acc[r] = fmaf(qv.y, kv.y, acc[r]);
                    acc[r] = fmaf(qv.z, kv.z, acc[r]);
                    acc[r] = fmaf(qv.w, kv.w, acc[r]);
                }
            }
            #pragma unroll
            for (int r = 0; r < 16; r++)
                if (acc[r] > bvl[r]) { bvl[r] = acc[r]; bil[r] = s; }
        }

        #pragma unroll
        for (int off = 16; off; off >>= 1) {
            #pragma unroll
            for (int r = 0; r < 16; r++) {
                float ov = __shfl_xor_sync(0xFFFFFFFFu, bvl[r], off);
                int   oi = __shfl_xor_sync(0xFFFFFFFFu, bil[r], off);
                if (ov > bvl[r] || (ov == bvl[r] && oi < bil[r])) { bvl[r] = ov; bil[r] = oi; }
            }
        }
        if (lane == 0) {
            #pragma unroll
            for (int r = 0; r < 16; r++) { rv[r][wid] = bvl[r]; rix[r][wid] = bil[r]; }
        }
        __syncthreads();
        if (tid < nr) {
            float fv = -FLT_MAX; int fi = S;
            #pragma unroll
            for (int w = 0; w < 8; w++) {
                float v = rv[tid][w]; int i = rix[tid][w];
                if (v > fv || (v == fv && i < fi)) { fv = v; fi = i; }
            }
            g_idx[g_flagged[base + tid]] = fi;
        }
        __syncthreads();
    }
}

// ---------------------------------------------------------------------------
// Gather read_out + winner vote (after rescore => final idx)
// ---------------------------------------------------------------------------
__global__ void gather_kernel(const float* __restrict__ vals,
                              float* __restrict__ out, int D) {
    int b  = blockIdx.x * 4 + (threadIdx.x >> 6);
    int c4 = threadIdx.x & 63;
    int idx = g_idx[b];
    float4 v = ((const float4*)(vals + (size_t)idx * D))[c4];
    ((float4*)(out + (size_t)b * D))[c4] = v;
    if (c4 == 0) atomicMax(&g_winner[idx], b);
}

// ---------------------------------------------------------------------------
// Gated scatter update
// ---------------------------------------------------------------------------
__global__ void update_kernel(const float* __restrict__ q,
                              const float* __restrict__ tgt,
                              const float* __restrict__ sur,
                              const float* __restrict__ keys,
                              const float* __restrict__ vals,
                              float* __restrict__ outK,
                              float* __restrict__ outV, int D) {
    int s = blockIdx.x;
    int d = threadIdx.x;
    int b = g_winner[s];
    float k = keys[(size_t)s * D + d];
    float v = vals[(size_t)s * D + d];
    if (b >= 0) {
        float g  = (1.0f / (1.0f + expf(-4.0f * sur[b]))) * LR;
        float om = 1.0f - g;
        outK[(size_t)s * D + d] = om * k + g * q[(size_t)b * D + d];
        outV[(size_t)s * D + d] = om * v + g * tgt[(size_t)b * D + d];
    } else {
        outK[(size_t)s * D + d] = k;
        outV[(size_t)s * D + d] = v;
    }
}

// ---------------------------------------------------------------------------
extern "C" void kernel_launch(void* const* d_in, const int* in_sizes, int n_in,
                              void* d_out, int out_size) {
    const float* query    = (const float*)d_in[0];
    const float* target   = (const float*)d_in[1];
    const float* surprise = (const float*)d_in[2];
    const float* keys     = (const float*)d_in[3];
    const float* vals     = (const float*)d_in[4];

    const int B = in_sizes[2];
    const int D = in_sizes[0] / B;     // 256
    const int S = in_sizes[3] / D;     // 1024

    float* out      = (float*)d_out;
    float* out_read = out;
    float* out_keys = out + (size_t)B * D;
    float* out_vals = out + (size_t)(B + S) * D;

    knorm_kernel<<<S, 256>>>(keys, S, D);

    cudaFuncSetAttribute(score_argmax_kernel,
                         cudaFuncAttributeMaxDynamicSharedMemorySize, SM_TOTAL);
    score_argmax_kernel<<<B / 128, 256, SM_TOTAL>>>(query, B, S);

    rescore_kernel<<<1024, 256>>>(query, S);

    gather_kernel<<<B / 4, 256>>>(vals, out_read, D);

    update_kernel<<<S, 256>>>(query, target, surprise, keys, vals,
                              out_keys, out_vals, D);
}